// round 1
// baseline (speedup 1.0000x reference)
#include <cuda_runtime.h>

#define NB   64
#define NV   4096
#define NFEAT 16
#define NA   8
#define NP   16
#define NOUT 16
#define SPLIT 4
#define CH   256

// scratch: per-batch aggregated means  agg[b][a][p]
__device__ float g_agg[NB * NA * NP];

__global__ void k_zero() {
    int i = blockIdx.x * blockDim.x + threadIdx.x;
    if (i < NB * NA * NP) g_agg[i] = 0.0f;
}

// ---------------------------------------------------------------------------
// Pass 1: agg[b,a,p] = (1/V) * sum_v ew[b,v,a] * feat[b,v,p]
// grid = NB*SPLIT blocks, 256 threads. Each block covers NV/SPLIT vertices.
// ---------------------------------------------------------------------------
__global__ __launch_bounds__(256) void k_aggregate(
    const float* __restrict__ data, const int* __restrict__ num_vertex,
    const float* __restrict__ W_flr, const float* __restrict__ b_flr,
    const float* __restrict__ W_s, const float* __restrict__ b_s)
{
    __shared__ float4 sWf4[NFEAT][4];   // W_flr rows as float4
    __shared__ float4 sWs4[NFEAT][2];   // W_s rows as float4
    __shared__ float  sbf[NP];
    __shared__ float  sbs[NA];
    __shared__ float  sfeat[CH * 17];   // padded rows: conflict-free
    __shared__ float  sew[CH * 9];

    const int b     = blockIdx.x / SPLIT;
    const int split = blockIdx.x % SPLIT;
    const int t     = threadIdx.x;
    const int nv    = num_vertex[b];
    const int vblk  = split * (NV / SPLIT);
    if (vblk >= nv) return;   // uniform: whole block masked, contributes zero

    if (t < 64) {
        sWf4[t >> 2][t & 3] = ((const float4*)W_flr)[t];
    } else if (t < 96) {
        int u = t - 64;
        sWs4[u >> 1][u & 1] = ((const float4*)W_s)[u];
    }
    if (t < NP) sbf[t] = b_flr[t];
    if (t < NA) sbs[t] = b_s[t];
    __syncthreads();

    // reduction ownership: 64 owners x 4 vertex slices
    const int owner = t & 63;
    const int aa    = owner >> 3;            // 0..7
    const int p0    = (owner & 7) * 2;       // 0,2,..,14
    const int slice = t >> 6;                // 0..3  (64 vertices each)
    float acc0 = 0.0f, acc1 = 0.0f;

    for (int c = 0; c < (NV / SPLIT) / CH; ++c) {
        const int vb = vblk + c * CH;
        if (vb >= nv) break;                 // uniform
        const int v = vb + t;

        // ---- compute phase: this thread produces feat/ew for vertex v ----
        if (v < nv) {
            const float4* dp = (const float4*)(data + (b * NV + v) * NFEAT);
            float4 x0 = dp[0], x1 = dp[1], x2 = dp[2], x3 = dp[3];
            float x[16];
            x[0]=x0.x; x[1]=x0.y; x[2]=x0.z; x[3]=x0.w;
            x[4]=x1.x; x[5]=x1.y; x[6]=x1.z; x[7]=x1.w;
            x[8]=x2.x; x[9]=x2.y; x[10]=x2.z; x[11]=x2.w;
            x[12]=x3.x; x[13]=x3.y; x[14]=x3.z; x[15]=x3.w;

            #pragma unroll
            for (int pg = 0; pg < 4; ++pg) {
                float s0 = sbf[pg*4+0], s1 = sbf[pg*4+1];
                float s2 = sbf[pg*4+2], s3 = sbf[pg*4+3];
                #pragma unroll
                for (int f = 0; f < 16; ++f) {
                    float4 w = sWf4[f][pg];
                    s0 += x[f]*w.x; s1 += x[f]*w.y;
                    s2 += x[f]*w.z; s3 += x[f]*w.w;
                }
                sfeat[t*17 + pg*4+0] = s0;
                sfeat[t*17 + pg*4+1] = s1;
                sfeat[t*17 + pg*4+2] = s2;
                sfeat[t*17 + pg*4+3] = s3;
            }
            #pragma unroll
            for (int g = 0; g < 2; ++g) {
                float s0 = sbs[g*4+0], s1 = sbs[g*4+1];
                float s2 = sbs[g*4+2], s3 = sbs[g*4+3];
                #pragma unroll
                for (int f = 0; f < 16; ++f) {
                    float4 w = sWs4[f][g];
                    s0 += x[f]*w.x; s1 += x[f]*w.y;
                    s2 += x[f]*w.z; s3 += x[f]*w.w;
                }
                sew[t*9 + g*4+0] = __expf(-s0*s0);
                sew[t*9 + g*4+1] = __expf(-s1*s1);
                sew[t*9 + g*4+2] = __expf(-s2*s2);
                sew[t*9 + g*4+3] = __expf(-s3*s3);
            }
        } else {
            #pragma unroll
            for (int p = 0; p < 16; ++p) sfeat[t*17 + p] = 0.0f;
            #pragma unroll
            for (int a = 0; a < 8; ++a)  sew[t*9 + a] = 0.0f;
        }
        __syncthreads();

        // ---- reduce phase: owner accumulates over its 64-vertex slice ----
        const int v0 = slice * 64;
        #pragma unroll 8
        for (int i = 0; i < 64; ++i) {
            const int vv = v0 + i;
            const float w = sew[vv*9 + aa];
            acc0 += w * sfeat[vv*17 + p0];
            acc1 += w * sfeat[vv*17 + p0 + 1];
        }
        __syncthreads();
    }

    const float inv = 1.0f / (float)NV;
    atomicAdd(&g_agg[b * (NA*NP) + aa * NP + p0    ], acc0 * inv);
    atomicAdd(&g_agg[b * (NA*NP) + aa * NP + p0 + 1], acc1 * inv);
}

// ---------------------------------------------------------------------------
// Pass 2: M[b,a,n] = sum_p agg[b,a,p] W_out[a*P+p, n]  (per-block, tiny)
//         out[b,v,n] = mask * (sum_a ew[b,v,a] * M[b,a,n] + b_out[n])
// grid = NB * (NV/256) blocks, 256 threads, one vertex per thread.
// ---------------------------------------------------------------------------
__global__ __launch_bounds__(256) void k_output(
    const float* __restrict__ data, const int* __restrict__ num_vertex,
    const float* __restrict__ W_s, const float* __restrict__ b_s,
    const float* __restrict__ W_out, const float* __restrict__ b_out,
    float* __restrict__ out)
{
    __shared__ __align__(16) float sM[NA * NOUT];  // 8x16
    __shared__ float4 sWs4[NFEAT][2];
    __shared__ float  sbs[NA];
    __shared__ float  sbo[NOUT];

    const int bpb = NV / 256;
    const int b   = blockIdx.x / bpb;
    const int vb  = (blockIdx.x % bpb) * 256;
    const int t   = threadIdx.x;
    const int nv  = num_vertex[b];

    if (t < NA * NOUT) {
        const int a = t >> 4, n = t & 15;
        float s = 0.0f;
        #pragma unroll
        for (int p = 0; p < NP; ++p)
            s += g_agg[b*(NA*NP) + a*NP + p] * W_out[(a*NP + p)*NOUT + n];
        sM[t] = s;
    } else if (t < 160) {
        const int u = t - 128;
        sWs4[u >> 1][u & 1] = ((const float4*)W_s)[u];
    }
    if (t < NA)   sbs[t] = b_s[t];
    if (t < NOUT) sbo[t] = b_out[t];
    __syncthreads();

    const int v = vb + t;
    float4* op = (float4*)(out + (b * NV + v) * NOUT);

    if (v < nv) {
        const float4* dp = (const float4*)(data + (b * NV + v) * NFEAT);
        float4 x0 = dp[0], x1 = dp[1], x2 = dp[2], x3 = dp[3];
        float x[16];
        x[0]=x0.x; x[1]=x0.y; x[2]=x0.z; x[3]=x0.w;
        x[4]=x1.x; x[5]=x1.y; x[6]=x1.z; x[7]=x1.w;
        x[8]=x2.x; x[9]=x2.y; x[10]=x2.z; x[11]=x2.w;
        x[12]=x3.x; x[13]=x3.y; x[14]=x3.z; x[15]=x3.w;

        float ew[8];
        #pragma unroll
        for (int g = 0; g < 2; ++g) {
            float s0 = sbs[g*4+0], s1 = sbs[g*4+1];
            float s2 = sbs[g*4+2], s3 = sbs[g*4+3];
            #pragma unroll
            for (int f = 0; f < 16; ++f) {
                float4 w = sWs4[f][g];
                s0 += x[f]*w.x; s1 += x[f]*w.y;
                s2 += x[f]*w.z; s3 += x[f]*w.w;
            }
            ew[g*4+0] = __expf(-s0*s0);
            ew[g*4+1] = __expf(-s1*s1);
            ew[g*4+2] = __expf(-s2*s2);
            ew[g*4+3] = __expf(-s3*s3);
        }

        float4 o[4];
        #pragma unroll
        for (int j = 0; j < 4; ++j)
            o[j] = make_float4(sbo[j*4], sbo[j*4+1], sbo[j*4+2], sbo[j*4+3]);
        #pragma unroll
        for (int a = 0; a < NA; ++a) {
            const float w = ew[a];
            const float4* mrow = (const float4*)(sM + a * NOUT);
            #pragma unroll
            for (int j = 0; j < 4; ++j) {
                const float4 m = mrow[j];
                o[j].x += w * m.x; o[j].y += w * m.y;
                o[j].z += w * m.z; o[j].w += w * m.w;
            }
        }
        op[0] = o[0]; op[1] = o[1]; op[2] = o[2]; op[3] = o[3];
    } else {
        const float4 z = make_float4(0.f, 0.f, 0.f, 0.f);
        op[0] = z; op[1] = z; op[2] = z; op[3] = z;
    }
}

extern "C" void kernel_launch(void* const* d_in, const int* in_sizes, int n_in,
                              void* d_out, int out_size) {
    const float* data       = (const float*)d_in[0];
    const int*   num_vertex = (const int*)  d_in[1];
    const float* W_flr      = (const float*)d_in[2];
    const float* b_flr      = (const float*)d_in[3];
    const float* W_s        = (const float*)d_in[4];
    const float* b_s        = (const float*)d_in[5];
    const float* W_out      = (const float*)d_in[6];
    const float* b_out      = (const float*)d_in[7];
    float* out = (float*)d_out;

    k_zero<<<(NB*NA*NP + 255)/256, 256>>>();
    k_aggregate<<<NB * SPLIT, 256>>>(data, num_vertex, W_flr, b_flr, W_s, b_s);
    k_output<<<NB * (NV/256), 256>>>(data, num_vertex, W_s, b_s, W_out, b_out, out);
}